// round 2
// baseline (speedup 1.0000x reference)
#include <cuda_runtime.h>
#include <math.h>

#define NQP   64
#define MQP   128
#define NP    2080
#define NH    8192
#define NOUT  10464
#define QPIT  50

__device__ float g_h1[1024 * 1024];
__device__ float g_h2[1024 * 1024];
__device__ float g_out[1024 * NOUT];

// ---------------------------------------------------------------------------
// Classic 128x128x8 SGEMM, 256 threads, 8x8 register tile.
// C[M,N] = act(A[M,K] @ B[K,N] + bias[N]) ; act = relu if doRelu.
// M,K multiples of 128/8 here; N guarded (GEMM3 has N=10464).
// ---------------------------------------------------------------------------
__global__ __launch_bounds__(256) void sgemm_kernel(
    const float* __restrict__ A, const float* __restrict__ B,
    const float* __restrict__ bias, float* __restrict__ C,
    int M, int N, int K, int doRelu)
{
    __shared__ float As[8][128];
    __shared__ float Bs[8][128];
    const int tid = threadIdx.x;
    const int tx = tid & 15;
    const int ty = tid >> 4;
    const int rowBase = blockIdx.y * 128;
    const int colBase = blockIdx.x * 128;

    const int aRow = tid >> 1;
    const int aCol = (tid & 1) * 4;
    const int bRow = tid >> 5;
    const int bCol = (tid & 31) * 4;

    float acc[8][8];
#pragma unroll
    for (int i = 0; i < 8; i++)
#pragma unroll
        for (int j = 0; j < 8; j++) acc[i][j] = 0.f;

    for (int k0 = 0; k0 < K; k0 += 8) {
        float4 av = *(const float4*)(A + (size_t)(rowBase + aRow) * K + k0 + aCol);
        As[aCol + 0][aRow] = av.x;
        As[aCol + 1][aRow] = av.y;
        As[aCol + 2][aRow] = av.z;
        As[aCol + 3][aRow] = av.w;

        int bc = colBase + bCol;
        const float* Bp = B + (size_t)(k0 + bRow) * N + bc;
        float4 bv;
        if (bc + 3 < N) {
            bv = *(const float4*)Bp;
        } else {
            bv.x = (bc + 0 < N) ? Bp[0] : 0.f;
            bv.y = (bc + 1 < N) ? Bp[1] : 0.f;
            bv.z = (bc + 2 < N) ? Bp[2] : 0.f;
            bv.w = (bc + 3 < N) ? Bp[3] : 0.f;
        }
        *(float4*)&Bs[bRow][bCol] = bv;
        __syncthreads();

#pragma unroll
        for (int kk = 0; kk < 8; kk++) {
            float4 a0 = *(const float4*)&As[kk][ty * 8];
            float4 a1 = *(const float4*)&As[kk][ty * 8 + 4];
            float4 b0 = *(const float4*)&Bs[kk][tx * 8];
            float4 b1 = *(const float4*)&Bs[kk][tx * 8 + 4];
            float ar[8] = {a0.x, a0.y, a0.z, a0.w, a1.x, a1.y, a1.z, a1.w};
            float br[8] = {b0.x, b0.y, b0.z, b0.w, b1.x, b1.y, b1.z, b1.w};
#pragma unroll
            for (int i = 0; i < 8; i++)
#pragma unroll
                for (int j = 0; j < 8; j++)
                    acc[i][j] += ar[i] * br[j];
        }
        __syncthreads();
    }

#pragma unroll
    for (int i = 0; i < 8; i++) {
        int r = rowBase + ty * 8 + i;
#pragma unroll
        for (int j = 0; j < 8; j++) {
            int c = colBase + tx * 8 + j;
            if (c < N) {
                float v = acc[i][j] + bias[c];
                if (doRelu) v = fmaxf(v, 0.f);
                C[(size_t)r * N + c] = v;
            }
        }
    }
}

// ---------------------------------------------------------------------------
// Per-batch QP solver. One CTA per batch element, 128 threads.
// smem (floats): Hs 8192 | Ainv 64*65 | Ls 2080 | vectors/scratch
// H stored [128][64] unpadded:
//   H·v   : thread m, skewed k-index -> bank (k+m)&31, conflict-free
//   Hᵀ·w  : thread n, loop m, consecutive addresses, conflict-free
// Ainv stride 65: column-parallel Gauss-Jordan conflict-free; Minv matvec
// uses symmetry (reads Minv[k][n], consecutive).
// ---------------------------------------------------------------------------
#define SOLVER_SMEM_FLOATS (8192 + 4160 + 2080 + 64 + 128 + 64 + 64 + 64 + 128 + 128 + 64 + 64 + 64 + 128 + 4)

__global__ __launch_bounds__(128) void solver_kernel(
    const float* __restrict__ out, float* __restrict__ xs)
{
    extern __shared__ float sm[];
    float* Hs   = sm;             // 8192  : H [128][64]
    float* Ainv = Hs + 8192;      // 4160  : A then Minv [64][65]
    float* Ls   = Ainv + 4160;    // 2080  : packed tril L
    float* v64  = Ls + 2080;      // 64
    float* w128 = v64 + 64;       // 128
    float* t64  = w128 + 128;     // 64
    float* colk = t64 + 64;       // 64
    float* q64  = colk + 64;      // 64
    float* b128 = q64 + 64;       // 128
    float* lam  = b128 + 128;     // 128
    float* xp   = lam + 128;      // 64
    float* xbar = xp + 64;        // 64
    float* rhs  = xbar + 64;      // 64
    float* red  = rhs + 64;       // 128
    float* scal = red + 128;      // 4

    const int tid = threadIdx.x;
    const float* Go = out + (size_t)blockIdx.x * NOUT;

    for (int i = tid; i < NH; i += 128) Hs[i] = Go[NP + NQP + i];
    for (int i = tid; i < NP; i += 128) Ls[i] = Go[i];
    if (tid < NQP) {
        q64[tid] = Go[NP + tid];
        xp[tid] = 0.f;
        xbar[tid] = 0.f;
        v64[tid] = 0.125f;  // 1/sqrt(64)
    }
    b128[tid] = Go[NP + NQP + NH + tid];
    lam[tid] = 0.f;
    __syncthreads();

    // softplus on L diagonal: L[d] = sqrt(0.01) + softplus(L[d])
    if (tid < NQP) {
        int d = tid * (tid + 1) / 2 + tid;
        float x = Ls[d];
        float sp = (x > 20.f) ? x : log1pf(expf(x));
        Ls[d] = 0.1f + sp;
    }

    // ---- power iteration: v <- normalize(H^T H v), 10 iterations ----
    for (int it = 0; it < 10; ++it) {
        __syncthreads();
        {
            float a0 = 0, a1 = 0, a2 = 0, a3 = 0;
            const float* Hr = Hs + tid * 64;
#pragma unroll
            for (int kk = 0; kk < 64; kk += 4) {
                int j0 = (kk + tid) & 63, j1 = (kk + 1 + tid) & 63;
                int j2 = (kk + 2 + tid) & 63, j3 = (kk + 3 + tid) & 63;
                a0 += Hr[j0] * v64[j0];
                a1 += Hr[j1] * v64[j1];
                a2 += Hr[j2] * v64[j2];
                a3 += Hr[j3] * v64[j3];
            }
            w128[tid] = (a0 + a1) + (a2 + a3);
        }
        __syncthreads();
        if (tid < 64) {
            float a0 = 0, a1 = 0, a2 = 0, a3 = 0;
#pragma unroll
            for (int m = 0; m < 128; m += 4) {
                a0 += Hs[m * 64 + tid] * w128[m];
                a1 += Hs[(m + 1) * 64 + tid] * w128[m + 1];
                a2 += Hs[(m + 2) * 64 + tid] * w128[m + 2];
                a3 += Hs[(m + 3) * 64 + tid] * w128[m + 3];
            }
            float u = (a0 + a1) + (a2 + a3);
            t64[tid] = u;
            red[tid] = u * u;
        }
        __syncthreads();
        if (tid < 32) {
            float s = red[tid] + red[tid + 32];
#pragma unroll
            for (int o = 16; o; o >>= 1) s += __shfl_down_sync(0xffffffffu, s, o);
            if (tid == 0) scal[0] = sqrtf(s);
        }
        __syncthreads();
        if (tid < 64) v64[tid] = t64[tid] / (scal[0] + 1e-12f);
    }
    __syncthreads();

    // ---- sn = ||H v|| + 1e-6 ; tau = 0.9/sn ----
    {
        float a0 = 0, a1 = 0, a2 = 0, a3 = 0;
        const float* Hr = Hs + tid * 64;
#pragma unroll
        for (int kk = 0; kk < 64; kk += 4) {
            int j0 = (kk + tid) & 63, j1 = (kk + 1 + tid) & 63;
            int j2 = (kk + 2 + tid) & 63, j3 = (kk + 3 + tid) & 63;
            a0 += Hr[j0] * v64[j0];
            a1 += Hr[j1] * v64[j1];
            a2 += Hr[j2] * v64[j2];
            a3 += Hr[j3] * v64[j3];
        }
        float wv = (a0 + a1) + (a2 + a3);
        red[tid] = wv * wv;
    }
    __syncthreads();
    if (tid < 32) {
        float s = red[tid] + red[tid + 32] + red[tid + 64] + red[tid + 96];
#pragma unroll
        for (int o = 16; o; o >>= 1) s += __shfl_down_sync(0xffffffffu, s, o);
        if (tid == 0) scal[1] = 0.9f / (sqrtf(s) + 1e-6f);
    }
    __syncthreads();
    const float tau = scal[1];

    // ---- A = I + tau * L L^T (symmetric, stride 65) ----
    for (int p = tid; p < NP; p += 128) {
        int i = (int)((sqrtf(8.f * (float)p + 1.f) - 1.f) * 0.5f);
        while ((i + 1) * (i + 2) / 2 <= p) ++i;
        while (i * (i + 1) / 2 > p) --i;
        int j = p - i * (i + 1) / 2;
        const float* Li = Ls + i * (i + 1) / 2;
        const float* Lj = Ls + j * (j + 1) / 2;
        float s = 0.f;
        for (int k = 0; k <= j; k++) s += Li[k] * Lj[k];
        float a = tau * s + (i == j ? 1.f : 0.f);
        Ainv[i * 65 + j] = a;
        Ainv[j * 65 + i] = a;
    }
    __syncthreads();

    // ---- in-place Gauss-Jordan inverse (SPD, no pivoting) ----
    {
        const int j = tid & 63;
        const int s = tid >> 6;
        const int i0 = s * 32;
        for (int k = 0; k < 64; k++) {
            if (tid < 64) colk[tid] = Ainv[tid * 65 + k];
            __syncthreads();
            float pinv = 1.f / colk[k];
            float akjn = (j == k) ? pinv : Ainv[k * 65 + j] * pinv;
            __syncthreads();  // all reads of row k done before row-k write
            if (j == k) {
#pragma unroll 4
                for (int i = i0; i < i0 + 32; i++)
                    if (i != k) Ainv[i * 65 + k] = -colk[i] * pinv;
            } else {
#pragma unroll 4
                for (int i = i0; i < i0 + 32; i++)
                    if (i != k) Ainv[i * 65 + j] -= colk[i] * akjn;
            }
            if (s == 0) Ainv[k * 65 + j] = akjn;
            __syncthreads();
        }
    }

    // ---- 50 PDHG iterations ----
    for (int it = 0; it < QPIT; ++it) {
        // phase 1: lam = relu(lam - tau*(H xbar + b))   (128 threads)
        {
            float a0 = 0, a1 = 0, a2 = 0, a3 = 0;
            const float* Hr = Hs + tid * 64;
#pragma unroll
            for (int kk = 0; kk < 64; kk += 4) {
                int j0 = (kk + tid) & 63, j1 = (kk + 1 + tid) & 63;
                int j2 = (kk + 2 + tid) & 63, j3 = (kk + 3 + tid) & 63;
                a0 += Hr[j0] * xbar[j0];
                a1 += Hr[j1] * xbar[j1];
                a2 += Hr[j2] * xbar[j2];
                a3 += Hr[j3] * xbar[j3];
            }
            float hx = (a0 + a1) + (a2 + a3);
            float l = lam[tid] - tau * (hx + b128[tid]);
            lam[tid] = fmaxf(l, 0.f);
        }
        __syncthreads();
        // phase 2: rhs = xp + tau*(H^T lam - q)         (64 threads)
        if (tid < 64) {
            float a0 = 0, a1 = 0, a2 = 0, a3 = 0;
#pragma unroll
            for (int m = 0; m < 128; m += 4) {
                a0 += Hs[m * 64 + tid] * lam[m];
                a1 += Hs[(m + 1) * 64 + tid] * lam[m + 1];
                a2 += Hs[(m + 2) * 64 + tid] * lam[m + 2];
                a3 += Hs[(m + 3) * 64 + tid] * lam[m + 3];
            }
            float z = (a0 + a1) + (a2 + a3);
            rhs[tid] = xp[tid] + tau * (z - q64[tid]);
        }
        __syncthreads();
        // phase 3: xn = Minv rhs (Minv symmetric -> read [k][n], consecutive)
        if (tid < 64) {
            float a0 = 0, a1 = 0, a2 = 0, a3 = 0;
#pragma unroll
            for (int k = 0; k < 64; k += 4) {
                a0 += Ainv[k * 65 + tid] * rhs[k];
                a1 += Ainv[(k + 1) * 65 + tid] * rhs[k + 1];
                a2 += Ainv[(k + 2) * 65 + tid] * rhs[k + 2];
                a3 += Ainv[(k + 3) * 65 + tid] * rhs[k + 3];
            }
            float xn = (a0 + a1) + (a2 + a3);
            xbar[tid] = 2.f * xn - xp[tid];
            xp[tid] = xn;
        }
        __syncthreads();
    }

    if (tid < 64) xs[(size_t)blockIdx.x * NQP + tid] = xp[tid];
}

// ---------------------------------------------------------------------------
extern "C" void kernel_launch(void* const* d_in, const int* in_sizes, int n_in,
                              void* d_out, int out_size)
{
    const float* x  = (const float*)d_in[0];
    const float* W1 = (const float*)d_in[1];
    const float* b1 = (const float*)d_in[2];
    const float* W2 = (const float*)d_in[3];
    const float* b2 = (const float*)d_in[4];
    const float* W3 = (const float*)d_in[5];
    const float* b3 = (const float*)d_in[6];
    float* xs = (float*)d_out;

    float *h1, *h2, *obuf;
    cudaGetSymbolAddress((void**)&h1, g_h1);
    cudaGetSymbolAddress((void**)&h2, g_h2);
    cudaGetSymbolAddress((void**)&obuf, g_out);

    const int smemBytes = SOLVER_SMEM_FLOATS * (int)sizeof(float);
    cudaFuncSetAttribute(solver_kernel,
                         cudaFuncAttributeMaxDynamicSharedMemorySize, smemBytes);

    sgemm_kernel<<<dim3(8, 8), 256>>>(x, W1, b1, h1, 1024, 1024, 512, 1);
    sgemm_kernel<<<dim3(8, 8), 256>>>(h1, W2, b2, h2, 1024, 1024, 1024, 1);
    sgemm_kernel<<<dim3((NOUT + 127) / 128, 8), 256>>>(h2, W3, b3, obuf,
                                                       1024, NOUT, 1024, 0);
    solver_kernel<<<1024, 128, smemBytes>>>(obuf, xs);
}

// round 3
// speedup vs baseline: 1.2210x; 1.2210x over previous
#include <cuda_runtime.h>
#include <math.h>

#define NQP   64
#define MQP   128
#define NP    2080
#define NH    8192
#define NOUT  10464
#define QPIT  50
#define HSTR  68   // padded row stride for H in smem (floats)
#define ASTR  68   // padded row stride for A/Minv in smem (floats)

__device__ float g_h1[1024 * 1024];
__device__ float g_h2[1024 * 1024];
__device__ float g_out[1024 * NOUT];

// ---------------------------------------------------------------------------
// Classic 128x128x8 SGEMM, 256 threads, 8x8 register tile. (unchanged)
// ---------------------------------------------------------------------------
__global__ __launch_bounds__(256) void sgemm_kernel(
    const float* __restrict__ A, const float* __restrict__ B,
    const float* __restrict__ bias, float* __restrict__ C,
    int M, int N, int K, int doRelu)
{
    __shared__ float As[8][128];
    __shared__ float Bs[8][128];
    const int tid = threadIdx.x;
    const int tx = tid & 15;
    const int ty = tid >> 4;
    const int rowBase = blockIdx.y * 128;
    const int colBase = blockIdx.x * 128;

    const int aRow = tid >> 1;
    const int aCol = (tid & 1) * 4;
    const int bRow = tid >> 5;
    const int bCol = (tid & 31) * 4;

    float acc[8][8];
#pragma unroll
    for (int i = 0; i < 8; i++)
#pragma unroll
        for (int j = 0; j < 8; j++) acc[i][j] = 0.f;

    for (int k0 = 0; k0 < K; k0 += 8) {
        float4 av = *(const float4*)(A + (size_t)(rowBase + aRow) * K + k0 + aCol);
        As[aCol + 0][aRow] = av.x;
        As[aCol + 1][aRow] = av.y;
        As[aCol + 2][aRow] = av.z;
        As[aCol + 3][aRow] = av.w;

        int bc = colBase + bCol;
        const float* Bp = B + (size_t)(k0 + bRow) * N + bc;
        float4 bv;
        if (bc + 3 < N) {
            bv = *(const float4*)Bp;
        } else {
            bv.x = (bc + 0 < N) ? Bp[0] : 0.f;
            bv.y = (bc + 1 < N) ? Bp[1] : 0.f;
            bv.z = (bc + 2 < N) ? Bp[2] : 0.f;
            bv.w = (bc + 3 < N) ? Bp[3] : 0.f;
        }
        *(float4*)&Bs[bRow][bCol] = bv;
        __syncthreads();

#pragma unroll
        for (int kk = 0; kk < 8; kk++) {
            float4 a0 = *(const float4*)&As[kk][ty * 8];
            float4 a1 = *(const float4*)&As[kk][ty * 8 + 4];
            float4 b0 = *(const float4*)&Bs[kk][tx * 8];
            float4 b1 = *(const float4*)&Bs[kk][tx * 8 + 4];
            float ar[8] = {a0.x, a0.y, a0.z, a0.w, a1.x, a1.y, a1.z, a1.w};
            float br[8] = {b0.x, b0.y, b0.z, b0.w, b1.x, b1.y, b1.z, b1.w};
#pragma unroll
            for (int i = 0; i < 8; i++)
#pragma unroll
                for (int j = 0; j < 8; j++)
                    acc[i][j] += ar[i] * br[j];
        }
        __syncthreads();
    }

#pragma unroll
    for (int i = 0; i < 8; i++) {
        int r = rowBase + ty * 8 + i;
#pragma unroll
        for (int j = 0; j < 8; j++) {
            int c = colBase + tx * 8 + j;
            if (c < N) {
                float v = acc[i][j] + bias[c];
                if (doRelu) v = fmaxf(v, 0.f);
                C[(size_t)r * N + c] = v;
            }
        }
    }
}

// ---------------------------------------------------------------------------
// Per-batch QP solver v2. One CTA per batch, 128 threads.
//  - H rows in registers (Hrow[64]) for H·x products (broadcast-only smem).
//  - H in smem [128][68] for H^T products (conflict-free column reads).
//  - Minv columns split-k in registers (Mreg[32]) for the solve matvec.
//  - Inverse via symmetric SWEEP operator (lower triangle only, float4 rows,
//    junk chunk tails absorbed by padding / row-k rewrite). sweep(A) = -A^-1.
// ---------------------------------------------------------------------------
#define SOLVER_SMEM_FLOATS (8704 + 4352 + 64 + 128 + 64 + 64 + 128 + 64 + 64 + 128 + 8)

__global__ __launch_bounds__(128, 3) void solver_kernel(
    const float* __restrict__ out, float* __restrict__ xs)
{
    extern __shared__ float sm[];
    float* Hs   = sm;                 // 8704 : H [128][HSTR] (scratch for L first)
    float* Ainv = Hs + 8704;          // 4352 : P -> A -> swept(A) [64][ASTR], lower
    float* v64  = Ainv + 4352;        // 64
    float* w128 = v64 + 64;           // 128
    float* t64  = w128 + 128;         // 64
    float* colk = t64 + 64;           // 64
    float* lam  = colk + 64;          // 128
    float* xbar = lam + 128;          // 64
    float* rhs  = xbar + 64;          // 64
    float* red  = rhs + 64;           // 128
    float* scal = red + 128;          // 8

    const int tid = threadIdx.x;
    const int n   = tid & 63;
    const int s   = tid >> 6;
    const float* Go = out + (size_t)blockIdx.x * NOUT;

    // ---- stage L params into Hs scratch; softplus the diagonal ----
    for (int i = tid; i < NP; i += 128) Hs[i] = Go[i];
    __syncthreads();
    if (tid < 64) {
        int d = tid * (tid + 1) / 2 + tid;
        float xv = Hs[d];
        float sp = (xv > 20.f) ? xv : log1pf(expf(xv));
        Hs[d] = 0.1f + sp;
    }
    __syncthreads();

    // ---- P = L L^T, lower triangle only, into Ainv (stride ASTR) ----
    for (int p = tid; p < NP; p += 128) {
        int i = (int)((sqrtf(8.f * (float)p + 1.f) - 1.f) * 0.5f);
        while ((i + 1) * (i + 2) / 2 <= p) ++i;
        while (i * (i + 1) / 2 > p) --i;
        int j = p - i * (i + 1) / 2;
        const float* Li = Hs + i * (i + 1) / 2;
        const float* Lj = Hs + j * (j + 1) / 2;
        float acc = 0.f;
        for (int k = 0; k <= j; k++) acc += Li[k] * Lj[k];
        Ainv[i * ASTR + j] = acc;
    }
    __syncthreads();   // L no longer needed; Hs region reused for H

    // ---- load H (stride HSTR), b, q; init v ----
    for (int i = tid; i < NH; i += 128)
        Hs[(i >> 6) * HSTR + (i & 63)] = Go[NP + NQP + i];
    const float br = Go[NP + NQP + NH + tid];
    const float qr = (tid < 64) ? Go[NP + tid] : 0.f;
    if (tid < 64) v64[tid] = 0.125f;   // 1/sqrt(64)
    __syncthreads();

    // ---- H row -> registers ----
    float Hrow[64];
#pragma unroll
    for (int t = 0; t < 16; t++) {
        float4 h = *(const float4*)&Hs[tid * HSTR + 4 * t];
        Hrow[4 * t + 0] = h.x; Hrow[4 * t + 1] = h.y;
        Hrow[4 * t + 2] = h.z; Hrow[4 * t + 3] = h.w;
    }

    // ---- power iteration: v <- normalize(H^T H v), 10 iters ----
    for (int it = 0; it < 10; ++it) {
        // w = H v  (registers + broadcasts)
        float c0 = 0, c1 = 0, c2 = 0, c3 = 0;
#pragma unroll
        for (int t = 0; t < 16; t++) {
            float4 vv = *(const float4*)&v64[4 * t];
            c0 += Hrow[4 * t + 0] * vv.x;
            c1 += Hrow[4 * t + 1] * vv.y;
            c2 += Hrow[4 * t + 2] * vv.z;
            c3 += Hrow[4 * t + 3] * vv.w;
        }
        w128[tid] = (c0 + c1) + (c2 + c3);
        __syncthreads();
        // u = H^T w (split over m-halves; conflict-free column reads)
        {
            float a0 = 0, a1 = 0, a2 = 0, a3 = 0;
            const float* Hc = Hs + (s * 64) * HSTR + n;
            const float4* wv4 = (const float4*)(w128 + s * 64);
#pragma unroll
            for (int t = 0; t < 16; t++) {
                float4 wv = wv4[t];
                a0 += Hc[(4 * t + 0) * HSTR] * wv.x;
                a1 += Hc[(4 * t + 1) * HSTR] * wv.y;
                a2 += Hc[(4 * t + 2) * HSTR] * wv.z;
                a3 += Hc[(4 * t + 3) * HSTR] * wv.w;
            }
            red[tid] = (a0 + a1) + (a2 + a3);
        }
        __syncthreads();
        if (tid < 64) {
            float u = red[tid] + red[tid + 64];
            t64[tid] = u;
            red[tid] = u * u;
        }
        __syncthreads();
        if (tid < 32) {
            float ss = red[tid] + red[tid + 32];
#pragma unroll
            for (int o = 16; o; o >>= 1) ss += __shfl_down_sync(0xffffffffu, ss, o);
            if (tid == 0) scal[0] = 1.f / (sqrtf(ss) + 1e-12f);
        }
        __syncthreads();
        if (tid < 64) v64[tid] = t64[tid] * scal[0];
        __syncthreads();
    }

    // ---- sn = ||H v|| + 1e-6 ; tau = 0.9/sn ----
    {
        float c0 = 0, c1 = 0, c2 = 0, c3 = 0;
#pragma unroll
        for (int t = 0; t < 16; t++) {
            float4 vv = *(const float4*)&v64[4 * t];
            c0 += Hrow[4 * t + 0] * vv.x;
            c1 += Hrow[4 * t + 1] * vv.y;
            c2 += Hrow[4 * t + 2] * vv.z;
            c3 += Hrow[4 * t + 3] * vv.w;
        }
        float hv = (c0 + c1) + (c2 + c3);
        red[tid] = hv * hv;
    }
    __syncthreads();
    if (tid < 32) {
        float ss = red[tid] + red[tid + 32] + red[tid + 64] + red[tid + 96];
#pragma unroll
        for (int o = 16; o; o >>= 1) ss += __shfl_down_sync(0xffffffffu, ss, o);
        if (tid == 0) scal[1] = 0.9f / (sqrtf(ss) + 1e-6f);
    }
    __syncthreads();
    const float tau = scal[1];

    // ---- A = I + tau*P (lower triangle, in place) ----
    for (int p = tid; p < 64 * 64; p += 128) {
        int i = p >> 6, j = p & 63;
        if (j <= i)
            Ainv[i * ASTR + j] = tau * Ainv[i * ASTR + j] + (i == j ? 1.f : 0.f);
    }
    __syncthreads();

    // ---- symmetric sweep: A -> -A^{-1} (lower triangle, float4 chunks) ----
    {
        const int i = n;  // each of the 2 thread-halves works chunks c ≡ s (mod 2)
        for (int k = 0; k < 64; k++) {
            if (tid < 64)
                colk[tid] = (tid >= k) ? Ainv[tid * ASTR + k] : Ainv[k * ASTR + tid];
            __syncthreads();
            const float pinv = 1.f / colk[k];
            const float ci = colk[i] * pinv;
            for (int c = s; 4 * c <= i; c += 2) {
                float4 cj = *(const float4*)&colk[4 * c];       // broadcast
                float4 a = *(float4*)&Ainv[i * ASTR + 4 * c];   // chunk tail junk ok
                a.x -= ci * cj.x; a.y -= ci * cj.y;
                a.z -= ci * cj.z; a.w -= ci * cj.w;
                *(float4*)&Ainv[i * ASTR + 4 * c] = a;
            }
            __syncthreads();
            if (tid < 64) {   // rewrite row/col k from the snapshot
                if (tid > k)      Ainv[tid * ASTR + k] = colk[tid] * pinv;
                else if (tid < k) Ainv[k * ASTR + tid] = colk[tid] * pinv;
                else              Ainv[k * ASTR + k]   = -pinv;
            }
            __syncthreads();
        }
    }

    // ---- Minv piece -> registers: Mreg[t] = swept[32s+t][n] (negate at use) ----
    float Mreg[32];
    {
        const int base = s * 32;
#pragma unroll
        for (int t = 0; t < 32; t++) {
            int kk = base + t;
            Mreg[t] = (kk >= n) ? Ainv[kk * ASTR + n] : Ainv[n * ASTR + kk];
        }
    }

    // ---- 50 PDHG iterations ----
    float lamr = 0.f;
    float xpr = 0.f;
    if (tid < 64) xbar[tid] = 0.f;
    __syncthreads();

    for (int it = 0; it < QPIT; ++it) {
        // phase 1: lam = relu(lam - tau*(H xbar + b))  [registers + broadcasts]
        float c0 = 0, c1 = 0, c2 = 0, c3 = 0;
#pragma unroll
        for (int t = 0; t < 16; t++) {
            float4 xv = *(const float4*)&xbar[4 * t];
            c0 += Hrow[4 * t + 0] * xv.x;
            c1 += Hrow[4 * t + 1] * xv.y;
            c2 += Hrow[4 * t + 2] * xv.z;
            c3 += Hrow[4 * t + 3] * xv.w;
        }
        float hx = (c0 + c1) + (c2 + c3);
        lamr = fmaxf(lamr - tau * (hx + br), 0.f);
        lam[tid] = lamr;
        __syncthreads();

        // phase 2: z = H^T lam (split over m-halves)
        {
            float a0 = 0, a1 = 0, a2 = 0, a3 = 0;
            const float* Hc = Hs + (s * 64) * HSTR + n;
            const float4* lv4 = (const float4*)(lam + s * 64);
#pragma unroll
            for (int t = 0; t < 16; t++) {
                float4 lv = lv4[t];
                a0 += Hc[(4 * t + 0) * HSTR] * lv.x;
                a1 += Hc[(4 * t + 1) * HSTR] * lv.y;
                a2 += Hc[(4 * t + 2) * HSTR] * lv.z;
                a3 += Hc[(4 * t + 3) * HSTR] * lv.w;
            }
            red[tid] = (a0 + a1) + (a2 + a3);
        }
        __syncthreads();
        if (tid < 64)
            rhs[tid] = xpr + tau * ((red[tid] + red[tid + 64]) - qr);
        __syncthreads();

        // phase 3: xn = Minv rhs = -(swept) rhs, split-k in registers
        {
            float a0 = 0, a1 = 0, a2 = 0, a3 = 0;
            const float4* rv4 = (const float4*)(rhs + s * 32);
#pragma unroll
            for (int t = 0; t < 8; t++) {
                float4 rv = rv4[t];
                a0 += Mreg[4 * t + 0] * rv.x;
                a1 += Mreg[4 * t + 1] * rv.y;
                a2 += Mreg[4 * t + 2] * rv.z;
                a3 += Mreg[4 * t + 3] * rv.w;
            }
            red[tid] = (a0 + a1) + (a2 + a3);
        }
        __syncthreads();
        if (tid < 64) {
            float xn = -(red[tid] + red[tid + 64]);
            xbar[tid] = 2.f * xn - xpr;
            xpr = xn;
        }
        __syncthreads();
    }

    if (tid < 64) xs[(size_t)blockIdx.x * NQP + tid] = xpr;
}

// ---------------------------------------------------------------------------
extern "C" void kernel_launch(void* const* d_in, const int* in_sizes, int n_in,
                              void* d_out, int out_size)
{
    const float* x  = (const float*)d_in[0];
    const float* W1 = (const float*)d_in[1];
    const float* b1 = (const float*)d_in[2];
    const float* W2 = (const float*)d_in[3];
    const float* b2 = (const float*)d_in[4];
    const float* W3 = (const float*)d_in[5];
    const float* b3 = (const float*)d_in[6];
    float* xs = (float*)d_out;

    float *h1, *h2, *obuf;
    cudaGetSymbolAddress((void**)&h1, g_h1);
    cudaGetSymbolAddress((void**)&h2, g_h2);
    cudaGetSymbolAddress((void**)&obuf, g_out);

    const int smemBytes = SOLVER_SMEM_FLOATS * (int)sizeof(float);
    cudaFuncSetAttribute(solver_kernel,
                         cudaFuncAttributeMaxDynamicSharedMemorySize, smemBytes);

    sgemm_kernel<<<dim3(8, 8), 256>>>(x, W1, b1, h1, 1024, 1024, 512, 1);
    sgemm_kernel<<<dim3(8, 8), 256>>>(h1, W2, b2, h2, 1024, 1024, 1024, 1);
    sgemm_kernel<<<dim3((NOUT + 127) / 128, 8), 256>>>(h2, W3, b3, obuf,
                                                       1024, NOUT, 1024, 0);
    solver_kernel<<<1024, 128, smemBytes>>>(obuf, xs);
}

// round 9
// speedup vs baseline: 1.4720x; 1.2056x over previous
#include <cuda_runtime.h>
#include <cuda_bf16.h>
#include <math.h>
#include <stdint.h>

#define NQP   64
#define MQP   128
#define NP    2080
#define NH    8192
#define NOUT  10464
#define QPIT  50
#define HSTR  68
#define ASTR  68

#define HID   1024
#define INSZ  512
#define BATCH 1024

// ---------------- device scratch (no runtime alloc allowed) ----------------
__device__ __nv_bfloat16 g_xhi[BATCH * INSZ];
__device__ __nv_bfloat16 g_xlo[BATCH * INSZ];
__device__ __nv_bfloat16 g_w1thi[HID * INSZ];
__device__ __nv_bfloat16 g_w1tlo[HID * INSZ];
__device__ __nv_bfloat16 g_w2thi[HID * HID];
__device__ __nv_bfloat16 g_w2tlo[HID * HID];
__device__ __nv_bfloat16 g_w3thi[(size_t)NOUT * HID];
__device__ __nv_bfloat16 g_w3tlo[(size_t)NOUT * HID];
__device__ __nv_bfloat16 g_h1hi[BATCH * HID];
__device__ __nv_bfloat16 g_h1lo[BATCH * HID];
__device__ __nv_bfloat16 g_h2hi[BATCH * HID];
__device__ __nv_bfloat16 g_h2lo[BATCH * HID];
__device__ float g_out[(size_t)BATCH * NOUT];

// ---------------- baseline-PTX helpers (no 'a'-gated instructions) --------
__device__ __forceinline__ uint32_t smem_u32(const void* p) {
    uint32_t a;
    asm("{ .reg .u64 t; cvta.to.shared.u64 t, %1; cvt.u32.u64 %0, t; }" : "=r"(a) : "l"(p));
    return a;
}
__device__ __forceinline__ void cpasync16(uint32_t dst, const void* src, int srcsize) {
    asm volatile("cp.async.cg.shared.global [%0], [%1], 16, %2;"
                 :: "r"(dst), "l"(src), "r"(srcsize) : "memory");
}
#define CP_COMMIT() asm volatile("cp.async.commit_group;" ::: "memory")
#define CP_WAIT2()  asm volatile("cp.async.wait_group 2;" ::: "memory")

__device__ __forceinline__ void ldsm4(uint32_t* r, uint32_t addr) {
    asm volatile("ldmatrix.sync.aligned.m8n8.x4.shared.b16 {%0,%1,%2,%3}, [%4];"
                 : "=r"(r[0]), "=r"(r[1]), "=r"(r[2]), "=r"(r[3]) : "r"(addr));
}
__device__ __forceinline__ void mma16816(float* d, const uint32_t* a, const uint32_t* b) {
    asm volatile("mma.sync.aligned.m16n8k16.row.col.f32.bf16.bf16.f32 "
                 "{%0,%1,%2,%3}, {%4,%5,%6,%7}, {%8,%9}, {%0,%1,%2,%3};"
                 : "+f"(d[0]), "+f"(d[1]), "+f"(d[2]), "+f"(d[3])
                 : "r"(a[0]), "r"(a[1]), "r"(a[2]), "r"(a[3]), "r"(b[0]), "r"(b[1]));
}

// ---------------- input prep kernels ----------------
__global__ void split_kernel(const float* __restrict__ X,
                             __nv_bfloat16* __restrict__ Hi,
                             __nv_bfloat16* __restrict__ Lo, int n)
{
    for (int i = blockIdx.x * blockDim.x + threadIdx.x; i < n; i += gridDim.x * blockDim.x) {
        float v = X[i];
        __nv_bfloat16 h = __float2bfloat16_rn(v);
        Hi[i] = h;
        Lo[i] = __float2bfloat16_rn(v - __bfloat162float(h));
    }
}

// W: [K][N] fp32 -> T: [N][K] bf16 hi/lo (K,N multiples of 32)
__global__ void tsplit_kernel(const float* __restrict__ W,
                              __nv_bfloat16* __restrict__ Thi,
                              __nv_bfloat16* __restrict__ Tlo, int K, int N)
{
    __shared__ float tile[32][33];
    const int n0 = blockIdx.x * 32, k0 = blockIdx.y * 32;
    const int tx = threadIdx.x, ty = threadIdx.y;
#pragma unroll
    for (int r = 0; r < 4; r++)
        tile[ty + 8 * r][tx] = W[(size_t)(k0 + ty + 8 * r) * N + n0 + tx];
    __syncthreads();
#pragma unroll
    for (int r = 0; r < 4; r++) {
        int i = ty + 8 * r;
        float v = tile[tx][i];
        __nv_bfloat16 h = __float2bfloat16_rn(v);
        size_t o = (size_t)(n0 + i) * K + k0 + tx;
        Thi[o] = h;
        Tlo[o] = __float2bfloat16_rn(v - __bfloat162float(h));
    }
}

// ---------------- mma.sync split-bf16 GEMM ----------------
// D = Ahi·Bhi^T + Ahi·Blo^T + Alo·Bhi^T, fp32 accum in registers.
// A: [M,K] K-major bf16 (hi/lo); B: [N,K] K-major bf16 (hi/lo).
// smem per stage: 4 arrays (Ahi,Alo,Bhi,Blo) of 128 rows x 80B (4x16B used,
// 80B stride -> (5r+c)%8 covers all 8 16B-subbanks: ldmatrix conflict-free).
// mode 0: outF = acc + bias (col-guarded).  mode 1: relu+bias, hi/lo bf16 out.
#define ARRB  10240
#define STGB  (4 * ARRB)
#define GSMEM (3 * STGB)

__device__ __forceinline__ void load_stage(
    uint32_t sbase, int stage, int chunk,
    const __nv_bfloat16* __restrict__ Ahi, const __nv_bfloat16* __restrict__ Alo,
    const __nv_bfloat16* __restrict__ Bhi, const __nv_bfloat16* __restrict__ Blo,
    int row0, int col0, int K, int Nb, int tid)
{
    const int k0 = chunk * 32;
    const uint32_t st = sbase + stage * STGB;
#pragma unroll
    for (int a = 0; a < 4; a++) {
        const __nv_bfloat16* src = (a == 0) ? Ahi : (a == 1) ? Alo : (a == 2) ? Bhi : Blo;
        const int rb = (a < 2) ? row0 : col0;
        const int lim = (a < 2) ? (1 << 30) : Nb;
#pragma unroll
        for (int it = 0; it < 2; it++) {
            int idx = it * 256 + tid;
            int r = idx >> 2, c = idx & 3;
            int g = rb + r;
            int ok = (g < lim) ? 16 : 0;
            int gs = (g < lim) ? g : (lim - 1);
            cpasync16(st + a * ARRB + r * 80 + c * 16,
                      (const char*)src + ((size_t)gs * K + k0 + c * 8) * 2, ok);
        }
    }
}

__global__ __launch_bounds__(256, 1) void gemm_split_kernel(
    const __nv_bfloat16* __restrict__ Ahi, const __nv_bfloat16* __restrict__ Alo,
    const __nv_bfloat16* __restrict__ Bhi, const __nv_bfloat16* __restrict__ Blo,
    const float* __restrict__ bias,
    float* __restrict__ outF,
    __nv_bfloat16* __restrict__ outHi, __nv_bfloat16* __restrict__ outLo,
    int M, int N, int K, int mode)
{
    extern __shared__ char smem[];
    const uint32_t sbase = smem_u32(smem);
    const int tid = threadIdx.x;
    const int wid = tid >> 5, lane = tid & 31;
    const int warpM = wid >> 2, warpN = wid & 3;   // 2 x 4 warps
    const int row0 = blockIdx.y * 128, col0 = blockIdx.x * 128;
    const int nch = K >> 5;

    float acc[4][4][4];
#pragma unroll
    for (int i = 0; i < 4; i++)
#pragma unroll
        for (int j = 0; j < 4; j++)
#pragma unroll
            for (int k = 0; k < 4; k++) acc[i][j][k] = 0.f;

    // prefetch chunks 0,1
    load_stage(sbase, 0, 0, Ahi, Alo, Bhi, Blo, row0, col0, K, N, tid);
    CP_COMMIT();
    load_stage(sbase, 1, 1, Ahi, Alo, Bhi, Blo, row0, col0, K, N, tid);
    CP_COMMIT();

    // per-thread ldmatrix base offsets (within a stage)
    const uint32_t aOff = (uint32_t)((warpM * 64 + (lane & 15)) * 80 + (lane >> 4) * 16);
    const uint32_t bOff = (uint32_t)(2 * ARRB +
                          (warpN * 32 + ((lane >> 4) << 3) + (lane & 7)) * 80 +
                          ((lane >> 3) & 1) * 16);

    for (int c = 0; c < nch; c++) {
        if (c + 2 < nch)
            load_stage(sbase, (c + 2) % 3, c + 2, Ahi, Alo, Bhi, Blo, row0, col0, K, N, tid);
        CP_COMMIT();
        CP_WAIT2();
        __syncthreads();

        const uint32_t stg = sbase + (c % 3) * STGB;
#pragma unroll
        for (int ks = 0; ks < 2; ks++) {
            uint32_t Ah[4][4], Al[4][4], Bh[2][4], Bl[2][4];
#pragma unroll
            for (int mf = 0; mf < 4; mf++) {
                ldsm4(Ah[mf], stg + aOff + mf * 1280 + ks * 32);
                ldsm4(Al[mf], stg + ARRB + aOff + mf * 1280 + ks * 32);
            }
#pragma unroll
            for (int p = 0; p < 2; p++) {
                ldsm4(Bh[p], stg + bOff + p * 1280 + ks * 32);
                ldsm4(Bl[p], stg + ARRB + bOff + p * 1280 + ks * 32);
            }
#pragma unroll
            for (int mf = 0; mf < 4; mf++)
#pragma unroll
                for (int nf = 0; nf < 4; nf++) {
                    const uint32_t* bh = &Bh[nf >> 1][(nf & 1) * 2];
                    const uint32_t* bl = &Bl[nf >> 1][(nf & 1) * 2];
                    mma16816(acc[mf][nf], Ah[mf], bh);
                    mma16816(acc[mf][nf], Ah[mf], bl);
                    mma16816(acc[mf][nf], Al[mf], bh);
                }
        }
        __syncthreads();   // all warps done with buffer (c%3) before it is re-filled
    }

    // ---- epilogue ----
    const int m0 = row0 + warpM * 64;
    const int n0 = col0 + warpN * 32;
    const int rl = lane >> 2, cl = 2 * (lane & 3);
#pragma unroll
    for (int nf = 0; nf < 4; nf++) {
        const int cc = n0 + nf * 8 + cl;
        float bi0 = 0.f, bi1 = 0.f;
        if (cc < N) { bi0 = bias[cc]; bi1 = bias[cc + 1]; }
#pragma unroll
        for (int mf = 0; mf < 4; mf++) {
            const int rr = m0 + mf * 16 + rl;
            if (mode == 0) {
                if (cc < N) {
                    float2 v0 = make_float2(acc[mf][nf][0] + bi0, acc[mf][nf][1] + bi1);
                    float2 v1 = make_float2(acc[mf][nf][2] + bi0, acc[mf][nf][3] + bi1);
                    *(float2*)&outF[(size_t)rr * N + cc] = v0;
                    *(float2*)&outF[(size_t)(rr + 8) * N + cc] = v1;
                }
            } else {
#pragma unroll
                for (int h = 0; h < 2; h++) {
                    float v0 = fmaxf(acc[mf][nf][2 * h + 0] + bi0, 0.f);
                    float v1 = fmaxf(acc[mf][nf][2 * h + 1] + bi1, 0.f);
                    __nv_bfloat16 h0 = __float2bfloat16_rn(v0);
                    __nv_bfloat16 h1 = __float2bfloat16_rn(v1);
                    __nv_bfloat162 hp, lp;
                    hp.x = h0; hp.y = h1;
                    lp.x = __float2bfloat16_rn(v0 - __bfloat162float(h0));
                    lp.y = __float2bfloat16_rn(v1 - __bfloat162float(h1));
                    size_t o = (size_t)(rr + 8 * h) * N + cc;
                    *(uint32_t*)&outHi[o] = *(uint32_t*)&hp;
                    *(uint32_t*)&outLo[o] = *(uint32_t*)&lp;
                }
            }
        }
    }
}

// ---------------------------------------------------------------------------
// Per-batch QP solver (unchanged passing version).
// ---------------------------------------------------------------------------
#define SOLVER_SMEM_FLOATS (8704 + 4352 + 64 + 128 + 64 + 64 + 128 + 64 + 64 + 128 + 8)

__global__ __launch_bounds__(128, 3) void solver_kernel(
    const float* __restrict__ out, float* __restrict__ xs)
{
    extern __shared__ float sm[];
    float* Hs   = sm;
    float* Ainv = Hs + 8704;
    float* v64  = Ainv + 4352;
    float* w128 = v64 + 64;
    float* t64  = w128 + 128;
    float* colk = t64 + 64;
    float* lam  = colk + 64;
    float* xbar = lam + 128;
    float* rhs  = xbar + 64;
    float* red  = rhs + 64;
    float* scal = red + 128;

    const int tid = threadIdx.x;
    const int n   = tid & 63;
    const int s   = tid >> 6;
    const float* Go = out + (size_t)blockIdx.x * NOUT;

    for (int i = tid; i < NP; i += 128) Hs[i] = Go[i];
    __syncthreads();
    if (tid < 64) {
        int d = tid * (tid + 1) / 2 + tid;
        float xv = Hs[d];
        float sp = (xv > 20.f) ? xv : log1pf(expf(xv));
        Hs[d] = 0.1f + sp;
    }
    __syncthreads();

    for (int p = tid; p < NP; p += 128) {
        int i = (int)((sqrtf(8.f * (float)p + 1.f) - 1.f) * 0.5f);
        while ((i + 1) * (i + 2) / 2 <= p) ++i;
        while (i * (i + 1) / 2 > p) --i;
        int j = p - i * (i + 1) / 2;
        const float* Li = Hs + i * (i + 1) / 2;
        const float* Lj = Hs + j * (j + 1) / 2;
        float acc = 0.f;
        for (int k = 0; k <= j; k++) acc += Li[k] * Lj[k];
        Ainv[i * ASTR + j] = acc;
    }
    __syncthreads();

    for (int i = tid; i < NH; i += 128)
        Hs[(i >> 6) * HSTR + (i & 63)] = Go[NP + NQP + i];
    const float br = Go[NP + NQP + NH + tid];
    const float qr = (tid < 64) ? Go[NP + tid] : 0.f;
    if (tid < 64) v64[tid] = 0.125f;
    __syncthreads();

    float Hrow[64];
#pragma unroll
    for (int t = 0; t < 16; t++) {
        float4 h = *(const float4*)&Hs[tid * HSTR + 4 * t];
        Hrow[4 * t + 0] = h.x; Hrow[4 * t + 1] = h.y;
        Hrow[4 * t + 2] = h.z; Hrow[4 * t + 3] = h.w;
    }

    for (int it = 0; it < 10; ++it) {
        float c0 = 0, c1 = 0, c2 = 0, c3 = 0;
#pragma unroll
        for (int t = 0; t < 16; t++) {
            float4 vv = *(const float4*)&v64[4 * t];
            c0 += Hrow[4 * t + 0] * vv.x;
            c1 += Hrow[4 * t + 1] * vv.y;
            c2 += Hrow[4 * t + 2] * vv.z;
            c3 += Hrow[4 * t + 3] * vv.w;
        }
        w128[tid] = (c0 + c1) + (c2 + c3);
        __syncthreads();
        {
            float a0 = 0, a1 = 0, a2 = 0, a3 = 0;
            const float* Hc = Hs + (s * 64) * HSTR + n;
            const float4* wv4 = (const float4*)(w128 + s * 64);
#pragma unroll
            for (int t = 0; t < 16; t++) {
                float4 wv = wv4[t];
                a0 += Hc[(4 * t + 0) * HSTR] * wv.x;
                a1 += Hc[(4 * t + 1) * HSTR] * wv.y;
                a2 += Hc[(4 * t + 2) * HSTR] * wv.z;
                a3 += Hc[(4 * t + 3) * HSTR] * wv.w;
            }
            red[tid] = (a0 + a1) + (a2 + a3);
        }
        __syncthreads();
        if (tid < 64) {
            float u = red[tid] + red[tid + 64];
            t64[tid] = u;
            red[tid] = u * u;
        }
        __syncthreads();
        if (tid < 32) {
            float ss = red[tid] + red[tid + 32];
#pragma unroll
            for (int o = 16; o; o >>= 1) ss += __shfl_down_sync(0xffffffffu, ss, o);
            if (tid == 0) scal[0] = 1.f / (sqrtf(ss) + 1e-12f);
        }
        __syncthreads();
        if (tid < 64) v64[tid] = t64[tid] * scal[0];
        __syncthreads();
    }

    {
        float c0 = 0, c1 = 0, c2 = 0, c3 = 0;
#pragma unroll
        for (int t = 0; t < 16; t++) {
            float4 vv = *(const float4*)&v64[4 * t];
            c0 += Hrow[4 * t + 0] * vv.x;
            c1 += Hrow[4 * t + 1] * vv.y;
            c2 += Hrow[4 * t + 2] * vv.z;
            c3 += Hrow[4 * t + 3] * vv.w;
        }
        float hv = (c0 + c1) + (c2 + c3);
        red[tid] = hv * hv;
    }
    __syncthreads();
    if (tid < 32) {
        float ss = red[tid] + red[tid + 32] + red[tid + 64] + red[tid + 96];
#pragma unroll
        for (int o = 16; o; o >>= 1) ss += __shfl_down_sync(0xffffffffu, ss, o);
        if (tid == 0) scal[1] = 0.9f / (sqrtf(ss) + 1e-6f);
    }
    __syncthreads();
    const float tau = scal[1];

    for (int p = tid; p < 64 * 64; p += 128) {
        int i = p >> 6, j = p & 63;
        if (j <= i)
            Ainv[i * ASTR + j] = tau * Ainv[i * ASTR + j] + (i == j ? 1.f : 0.f);
    }
    __syncthreads();

    {
        const int i = n;
        for (int k = 0; k < 64; k++) {
            if (tid < 64)
                colk[tid] = (tid >= k) ? Ainv[tid * ASTR + k] : Ainv[k * ASTR + tid];
            __syncthreads();
            const float pinv = 1.f / colk[k];
            const float ci = colk[i] * pinv;
            for (int c = s; 4 * c <= i; c += 2) {
                float4 cj = *(const float4*)&colk[4 * c];
                float4 a = *(float4*)&Ainv[i * ASTR + 4 * c];
                a.x -= ci * cj.x; a.y -= ci * cj.y;
                a.z -= ci * cj.z; a.w -= ci * cj.w;
                *(float4*)&Ainv[i * ASTR + 4 * c] = a;
            }
            __syncthreads();
            if (tid < 64) {
                if (tid > k)      Ainv[tid * ASTR + k] = colk[tid] * pinv;
                else if (tid < k) Ainv[k * ASTR + tid] = colk[tid] * pinv;
                else              Ainv[k * ASTR + k]   = -pinv;
            }
            __syncthreads();
        }
    }

    float Mreg[32];
    {
        const int base = s * 32;
#pragma unroll
        for (int t = 0; t < 32; t++) {
            int kk = base + t;
            Mreg[t] = (kk >= n) ? Ainv[kk * ASTR + n] : Ainv[n * ASTR + kk];
        }
    }

    float lamr = 0.f;
    float xpr = 0.f;
    if (tid < 64) xbar[tid] = 0.f;
    __syncthreads();

    for (int it = 0; it < QPIT; ++it) {
        float c0 = 0, c1 = 0, c2 = 0, c3 = 0;
#pragma unroll
        for (int t = 0; t < 16; t++) {
            float4 xv = *(const float4*)&xbar[4 * t];
            c0 += Hrow[4 * t + 0] * xv.x;
            c1 += Hrow[4 * t + 1] * xv.y;
            c2 += Hrow[4 * t + 2] * xv.z;
            c3 += Hrow[4 * t + 3] * xv.w;
        }
        float hx = (c0 + c1) + (c2 + c3);
        lamr = fmaxf(lamr - tau * (hx + br), 0.f);
        lam[tid] = lamr;
        __syncthreads();

        {
            float a0 = 0, a1 = 0, a2 = 0, a3 = 0;
            const float* Hc = Hs + (s * 64) * HSTR + n;
            const float4* lv4 = (const float4*)(lam + s * 64);
#pragma unroll
            for (int t = 0; t < 16; t++) {
                float4 lv = lv4[t];
                a0 += Hc[(4 * t + 0) * HSTR] * lv.x;
                a1 += Hc[(4 * t + 1) * HSTR] * lv.y;
                a2 += Hc[(4 * t + 2) * HSTR] * lv.z;
                a3 += Hc[(4 * t + 3) * HSTR] * lv.w;
            }
            red[tid] = (a0 + a1) + (a2 + a3);
        }
        __syncthreads();
        if (tid < 64)
            rhs[tid] = xpr + tau * ((red[tid] + red[tid + 64]) - qr);
        __syncthreads();

        {
            float a0 = 0, a1 = 0, a2 = 0, a3 = 0;
            const float4* rv4 = (const float4*)(rhs + s * 32);
#pragma unroll
            for (int t = 0; t < 8; t++) {
                float4 rv = rv4[t];
                a0 += Mreg[4 * t + 0] * rv.x;
                a1 += Mreg[4 * t + 1] * rv.y;
                a2 += Mreg[4 * t + 2] * rv.z;
                a3 += Mreg[4 * t + 3] * rv.w;
            }
            red[tid] = (a0 + a1) + (a2 + a3);
        }
        __syncthreads();
        if (tid < 64) {
            float xn = -(red[tid] + red[tid + 64]);
            xbar[tid] = 2.f * xn - xpr;
            xpr = xn;
        }
        __syncthreads();
    }

    if (tid < 64) xs[(size_t)blockIdx.x * NQP + tid] = xpr;
}

// ---------------------------------------------------------------------------
extern "C" void kernel_launch(void* const* d_in, const int* in_sizes, int n_in,
                              void* d_out, int out_size)
{
    const float* x  = (const float*)d_in[0];
    const float* W1 = (const float*)d_in[1];
    const float* b1 = (const float*)d_in[2];
    const float* W2 = (const float*)d_in[3];
    const float* b2 = (const float*)d_in[4];
    const float* W3 = (const float*)d_in[5];
    const float* b3 = (const float*)d_in[6];
    float* xs = (float*)d_out;

    __nv_bfloat16 *xhi, *xlo, *w1h, *w1l, *w2h, *w2l, *w3h, *w3l;
    __nv_bfloat16 *h1h, *h1l, *h2h, *h2l;
    float* obuf;
    cudaGetSymbolAddress((void**)&xhi, g_xhi);
    cudaGetSymbolAddress((void**)&xlo, g_xlo);
    cudaGetSymbolAddress((void**)&w1h, g_w1thi);
    cudaGetSymbolAddress((void**)&w1l, g_w1tlo);
    cudaGetSymbolAddress((void**)&w2h, g_w2thi);
    cudaGetSymbolAddress((void**)&w2l, g_w2tlo);
    cudaGetSymbolAddress((void**)&w3h, g_w3thi);
    cudaGetSymbolAddress((void**)&w3l, g_w3tlo);
    cudaGetSymbolAddress((void**)&h1h, g_h1hi);
    cudaGetSymbolAddress((void**)&h1l, g_h1lo);
    cudaGetSymbolAddress((void**)&h2h, g_h2hi);
    cudaGetSymbolAddress((void**)&h2l, g_h2lo);
    cudaGetSymbolAddress((void**)&obuf, g_out);

    cudaFuncSetAttribute(gemm_split_kernel,
                         cudaFuncAttributeMaxDynamicSharedMemorySize, GSMEM);
    const int ssmem = SOLVER_SMEM_FLOATS * (int)sizeof(float);
    cudaFuncSetAttribute(solver_kernel,
                         cudaFuncAttributeMaxDynamicSharedMemorySize, ssmem);

    // input prep: split x; transpose+split weights
    split_kernel<<<512, 256>>>(x, xhi, xlo, BATCH * INSZ);
    tsplit_kernel<<<dim3(HID / 32, INSZ / 32), dim3(32, 8)>>>(W1, w1h, w1l, INSZ, HID);
    tsplit_kernel<<<dim3(HID / 32, HID / 32), dim3(32, 8)>>>(W2, w2h, w2l, HID, HID);
    tsplit_kernel<<<dim3(NOUT / 32, HID / 32), dim3(32, 8)>>>(W3, w3h, w3l, HID, NOUT);

    // MLP on tensor cores (mma.sync bf16, 3-term split)
    gemm_split_kernel<<<dim3(8, 8), 256, GSMEM>>>(
        xhi, xlo, w1h, w1l, b1, nullptr, h1h, h1l, BATCH, HID, INSZ, 1);
    gemm_split_kernel<<<dim3(8, 8), 256, GSMEM>>>(
        h1h, h1l, w2h, w2l, b2, nullptr, h2h, h2l, BATCH, HID, HID, 1);
    gemm_split_kernel<<<dim3((NOUT + 127) / 128, 8), 256, GSMEM>>>(
        h2h, h2l, w3h, w3l, b3, obuf, nullptr, nullptr, BATCH, NOUT, HID, 0);

    solver_kernel<<<1024, 128, ssmem>>>(obuf, xs);
}

// round 10
// speedup vs baseline: 1.5663x; 1.0641x over previous
#include <cuda_runtime.h>
#include <cuda_bf16.h>
#include <math.h>
#include <stdint.h>

#define NQP   64
#define MQP   128
#define NP    2080
#define NH    8192
#define NOUT  10464
#define QPIT  50
#define HSTR  68
#define ASTR  68

#define HID   1024
#define INSZ  512
#define BATCH 1024

// ---------------- device scratch (no runtime alloc allowed) ----------------
__device__ __nv_bfloat16 g_xhi[BATCH * INSZ];
__device__ __nv_bfloat16 g_xlo[BATCH * INSZ];
__device__ __nv_bfloat16 g_w1thi[HID * INSZ];
__device__ __nv_bfloat16 g_w1tlo[HID * INSZ];
__device__ __nv_bfloat16 g_w2thi[HID * HID];
__device__ __nv_bfloat16 g_w2tlo[HID * HID];
__device__ __nv_bfloat16 g_w3thi[(size_t)NOUT * HID];
__device__ __nv_bfloat16 g_w3tlo[(size_t)NOUT * HID];
__device__ __nv_bfloat16 g_h1hi[BATCH * HID];
__device__ __nv_bfloat16 g_h1lo[BATCH * HID];
__device__ __nv_bfloat16 g_h2hi[BATCH * HID];
__device__ __nv_bfloat16 g_h2lo[BATCH * HID];
__device__ float g_out[(size_t)BATCH * NOUT];

// ---------------- baseline-PTX helpers (no 'a'-gated instructions) --------
__device__ __forceinline__ uint32_t smem_u32(const void* p) {
    uint32_t a;
    asm("{ .reg .u64 t; cvta.to.shared.u64 t, %1; cvt.u32.u64 %0, t; }" : "=r"(a) : "l"(p));
    return a;
}
__device__ __forceinline__ void cpasync16(uint32_t dst, const void* src, int srcsize) {
    asm volatile("cp.async.cg.shared.global [%0], [%1], 16, %2;"
                 :: "r"(dst), "l"(src), "r"(srcsize) : "memory");
}
#define CP_COMMIT() asm volatile("cp.async.commit_group;" ::: "memory")
#define CP_WAIT1()  asm volatile("cp.async.wait_group 1;" ::: "memory")

__device__ __forceinline__ void ldsm4(uint32_t* r, uint32_t addr) {
    asm volatile("ldmatrix.sync.aligned.m8n8.x4.shared.b16 {%0,%1,%2,%3}, [%4];"
                 : "=r"(r[0]), "=r"(r[1]), "=r"(r[2]), "=r"(r[3]) : "r"(addr));
}
__device__ __forceinline__ void mma16816(float* d, const uint32_t* a, const uint32_t* b) {
    asm volatile("mma.sync.aligned.m16n8k16.row.col.f32.bf16.bf16.f32 "
                 "{%0,%1,%2,%3}, {%4,%5,%6,%7}, {%8,%9}, {%0,%1,%2,%3};"
                 : "+f"(d[0]), "+f"(d[1]), "+f"(d[2]), "+f"(d[3])
                 : "r"(a[0]), "r"(a[1]), "r"(a[2]), "r"(a[3]), "r"(b[0]), "r"(b[1]));
}

// ---------------- input prep kernels ----------------
__global__ void split_kernel(const float* __restrict__ X,
                             __nv_bfloat16* __restrict__ Hi,
                             __nv_bfloat16* __restrict__ Lo, int n)
{
    for (int i = blockIdx.x * blockDim.x + threadIdx.x; i < n; i += gridDim.x * blockDim.x) {
        float v = X[i];
        __nv_bfloat16 h = __float2bfloat16_rn(v);
        Hi[i] = h;
        Lo[i] = __float2bfloat16_rn(v - __bfloat162float(h));
    }
}

// W: [K][N] fp32 -> T: [N][K] bf16 hi/lo (K,N multiples of 32)
__global__ void tsplit_kernel(const float* __restrict__ W,
                              __nv_bfloat16* __restrict__ Thi,
                              __nv_bfloat16* __restrict__ Tlo, int K, int N)
{
    __shared__ float tile[32][33];
    const int n0 = blockIdx.x * 32, k0 = blockIdx.y * 32;
    const int tx = threadIdx.x, ty = threadIdx.y;
#pragma unroll
    for (int r = 0; r < 4; r++)
        tile[ty + 8 * r][tx] = W[(size_t)(k0 + ty + 8 * r) * N + n0 + tx];
    __syncthreads();
#pragma unroll
    for (int r = 0; r < 4; r++) {
        int i = ty + 8 * r;
        float v = tile[tx][i];
        __nv_bfloat16 h = __float2bfloat16_rn(v);
        size_t o = (size_t)(n0 + i) * K + k0 + tx;
        Thi[o] = h;
        Tlo[o] = __float2bfloat16_rn(v - __bfloat162float(h));
    }
}

// ---------------- mma.sync split-bf16 GEMM ----------------
// D = Ahi·Bhi^T + Ahi·Blo^T + Alo·Bhi^T, fp32 accum in registers.
// A: [M,K] K-major bf16 (hi/lo); B: [N,K] K-major bf16 (hi/lo).
// K-chunk 64, 2 stages. Per stage: 4 arrays (Ahi,Alo,Bhi,Blo) of 128 rows x
// 144B (128B data + 16B pad; 144=9*16 -> (9r+c)%8=(r+c)%8 covers all 8
// 16B-subbanks: ldmatrix conflict-free).
// MMA issued TERM-MAJOR: all 16 acc tiles per term -> no RAW chains on acc.
// mode 0: outF = acc + bias (col-guarded).  mode 1: relu+bias, hi/lo bf16 out.
#define ARRB  18432
#define STGB  (4 * ARRB)
#define GSMEM (2 * STGB)

__device__ __forceinline__ void load_stage(
    uint32_t sbase, int stage, int chunk,
    const __nv_bfloat16* __restrict__ Ahi, const __nv_bfloat16* __restrict__ Alo,
    const __nv_bfloat16* __restrict__ Bhi, const __nv_bfloat16* __restrict__ Blo,
    int row0, int col0, int K, int Nb, int tid)
{
    const int k0 = chunk * 64;
    const uint32_t st = sbase + stage * STGB;
#pragma unroll
    for (int a = 0; a < 4; a++) {
        const __nv_bfloat16* src = (a == 0) ? Ahi : (a == 1) ? Alo : (a == 2) ? Bhi : Blo;
        const int rb = (a < 2) ? row0 : col0;
        const int lim = (a < 2) ? (1 << 30) : Nb;
#pragma unroll
        for (int it = 0; it < 4; it++) {
            int idx = it * 256 + tid;
            int r = idx >> 3, c = idx & 7;
            int g = rb + r;
            int ok = (g < lim) ? 16 : 0;
            int gs = (g < lim) ? g : (lim - 1);
            cpasync16(st + a * ARRB + r * 144 + c * 16,
                      (const char*)src + ((size_t)gs * K + k0 + c * 8) * 2, ok);
        }
    }
}

__global__ __launch_bounds__(256, 1) void gemm_split_kernel(
    const __nv_bfloat16* __restrict__ Ahi, const __nv_bfloat16* __restrict__ Alo,
    const __nv_bfloat16* __restrict__ Bhi, const __nv_bfloat16* __restrict__ Blo,
    const float* __restrict__ bias,
    float* __restrict__ outF,
    __nv_bfloat16* __restrict__ outHi, __nv_bfloat16* __restrict__ outLo,
    int M, int N, int K, int mode)
{
    extern __shared__ char smem[];
    const uint32_t sbase = smem_u32(smem);
    const int tid = threadIdx.x;
    const int wid = tid >> 5, lane = tid & 31;
    const int warpM = wid >> 2, warpN = wid & 3;   // 2 x 4 warps
    const int row0 = blockIdx.y * 128, col0 = blockIdx.x * 128;
    const int nch = K >> 6;

    float acc[4][4][4];
#pragma unroll
    for (int i = 0; i < 4; i++)
#pragma unroll
        for (int j = 0; j < 4; j++)
#pragma unroll
            for (int k = 0; k < 4; k++) acc[i][j][k] = 0.f;

    // prefetch chunks 0,1
    load_stage(sbase, 0, 0, Ahi, Alo, Bhi, Blo, row0, col0, K, N, tid);
    CP_COMMIT();
    load_stage(sbase, 1, 1, Ahi, Alo, Bhi, Blo, row0, col0, K, N, tid);
    CP_COMMIT();

    // per-thread ldmatrix base offsets (within a stage, stride 144B)
    const uint32_t aOff = (uint32_t)((warpM * 64 + (lane & 15)) * 144 + (lane >> 4) * 16);
    const uint32_t bOff = (uint32_t)(2 * ARRB +
                          (warpN * 32 + ((lane >> 4) << 3) + (lane & 7)) * 144 +
                          ((lane >> 3) & 1) * 16);

    for (int c = 0; c < nch; c++) {
        CP_WAIT1();
        __syncthreads();

        const uint32_t stg = sbase + (c & 1) * STGB;
#pragma unroll
        for (int ks = 0; ks < 4; ks++) {
            uint32_t Ah[4][4], Al[4][4], Bh[2][4], Bl[2][4];
#pragma unroll
            for (int mf = 0; mf < 4; mf++) {
                ldsm4(Ah[mf], stg + aOff + mf * 2304 + ks * 32);
                ldsm4(Al[mf], stg + ARRB + aOff + mf * 2304 + ks * 32);
            }
#pragma unroll
            for (int p = 0; p < 2; p++) {
                ldsm4(Bh[p], stg + bOff + p * 2304 + ks * 32);
                ldsm4(Bl[p], stg + ARRB + bOff + p * 2304 + ks * 32);
            }
            // term-major: 16 independent accumulators between reuse
#pragma unroll
            for (int mf = 0; mf < 4; mf++)
#pragma unroll
                for (int nf = 0; nf < 4; nf++)
                    mma16816(acc[mf][nf], Ah[mf], &Bh[nf >> 1][(nf & 1) * 2]);
#pragma unroll
            for (int mf = 0; mf < 4; mf++)
#pragma unroll
                for (int nf = 0; nf < 4; nf++)
                    mma16816(acc[mf][nf], Ah[mf], &Bl[nf >> 1][(nf & 1) * 2]);
#pragma unroll
            for (int mf = 0; mf < 4; mf++)
#pragma unroll
                for (int nf = 0; nf < 4; nf++)
                    mma16816(acc[mf][nf], Al[mf], &Bh[nf >> 1][(nf & 1) * 2]);
        }
        __syncthreads();   // all warps done reading stage (c&1)
        if (c + 2 < nch)
            load_stage(sbase, c & 1, c + 2, Ahi, Alo, Bhi, Blo, row0, col0, K, N, tid);
        CP_COMMIT();
    }

    // ---- epilogue ----
    const int m0 = row0 + warpM * 64;
    const int n0 = col0 + warpN * 32;
    const int rl = lane >> 2, cl = 2 * (lane & 3);
#pragma unroll
    for (int nf = 0; nf < 4; nf++) {
        const int cc = n0 + nf * 8 + cl;
        float bi0 = 0.f, bi1 = 0.f;
        if (cc < N) { bi0 = bias[cc]; bi1 = bias[cc + 1]; }
#pragma unroll
        for (int mf = 0; mf < 4; mf++) {
            const int rr = m0 + mf * 16 + rl;
            if (mode == 0) {
                if (cc < N) {
                    float2 v0 = make_float2(acc[mf][nf][0] + bi0, acc[mf][nf][1] + bi1);
                    float2 v1 = make_float2(acc[mf][nf][2] + bi0, acc[mf][nf][3] + bi1);
                    *(float2*)&outF[(size_t)rr * N + cc] = v0;
                    *(float2*)&outF[(size_t)(rr + 8) * N + cc] = v1;
                }
            } else {
#pragma unroll
                for (int h = 0; h < 2; h++) {
                    float v0 = fmaxf(acc[mf][nf][2 * h + 0] + bi0, 0.f);
                    float v1 = fmaxf(acc[mf][nf][2 * h + 1] + bi1, 0.f);
                    __nv_bfloat16 h0 = __float2bfloat16_rn(v0);
                    __nv_bfloat16 h1 = __float2bfloat16_rn(v1);
                    __nv_bfloat162 hp, lp;
                    hp.x = h0; hp.y = h1;
                    lp.x = __float2bfloat16_rn(v0 - __bfloat162float(h0));
                    lp.y = __float2bfloat16_rn(v1 - __bfloat162float(h1));
                    size_t o = (size_t)(rr + 8 * h) * N + cc;
                    *(uint32_t*)&outHi[o] = *(uint32_t*)&hp;
                    *(uint32_t*)&outLo[o] = *(uint32_t*)&lp;
                }
            }
        }
    }
}

// ---------------------------------------------------------------------------
// Per-batch QP solver (unchanged passing version).
// ---------------------------------------------------------------------------
#define SOLVER_SMEM_FLOATS (8704 + 4352 + 64 + 128 + 64 + 64 + 128 + 64 + 64 + 128 + 8)

__global__ __launch_bounds__(128, 3) void solver_kernel(
    const float* __restrict__ out, float* __restrict__ xs)
{
    extern __shared__ float sm[];
    float* Hs   = sm;
    float* Ainv = Hs + 8704;
    float* v64  = Ainv + 4352;
    float* w128 = v64 + 64;
    float* t64  = w128 + 128;
    float* colk = t64 + 64;
    float* lam  = colk + 64;
    float* xbar = lam + 128;
    float* rhs  = xbar + 64;
    float* red  = rhs + 64;
    float* scal = red + 128;

    const int tid = threadIdx.x;
    const int n   = tid & 63;
    const int s   = tid >> 6;
    const float* Go = out + (size_t)blockIdx.x * NOUT;

    for (int i = tid; i < NP; i += 128) Hs[i] = Go[i];
    __syncthreads();
    if (tid < 64) {
        int d = tid * (tid + 1) / 2 + tid;
        float xv = Hs[d];
        float sp = (xv > 20.f) ? xv : log1pf(expf(xv));
        Hs[d] = 0.1f + sp;
    }
    __syncthreads();

    for (int p = tid; p < NP; p += 128) {
        int i = (int)((sqrtf(8.f * (float)p + 1.f) - 1.f) * 0.5f);
        while ((i + 1) * (i + 2) / 2 <= p) ++i;
        while (i * (i + 1) / 2 > p) --i;
        int j = p - i * (i + 1) / 2;
        const float* Li = Hs + i * (i + 1) / 2;
        const float* Lj = Hs + j * (j + 1) / 2;
        float acc = 0.f;
        for (int k = 0; k <= j; k++) acc += Li[k] * Lj[k];
        Ainv[i * ASTR + j] = acc;
    }
    __syncthreads();

    for (int i = tid; i < NH; i += 128)
        Hs[(i >> 6) * HSTR + (i & 63)] = Go[NP + NQP + i];
    const float br = Go[NP + NQP + NH + tid];
    const float qr = (tid < 64) ? Go[NP + tid] : 0.f;
    if (tid < 64) v64[tid] = 0.125f;
    __syncthreads();

    float Hrow[64];
#pragma unroll
    for (int t = 0; t < 16; t++) {
        float4 h = *(const float4*)&Hs[tid * HSTR + 4 * t];
        Hrow[4 * t + 0] = h.x; Hrow[4 * t + 1] = h.y;
        Hrow[4 * t + 2] = h.z; Hrow[4 * t + 3] = h.w;
    }

    for (int it = 0; it < 10; ++it) {
        float c0 = 0, c1 = 0, c2 = 0, c3 = 0;
#pragma unroll
        for (int t = 0; t < 16; t++) {
            float4 vv = *(const float4*)&v64[4 * t];
            c0 += Hrow[4 * t + 0] * vv.x;
            c1 += Hrow[4 * t + 1] * vv.y;
            c2 += Hrow[4 * t + 2] * vv.z;
            c3 += Hrow[4 * t + 3] * vv.w;
        }
        w128[tid] = (c0 + c1) + (c2 + c3);
        __syncthreads();
        {
            float a0 = 0, a1 = 0, a2 = 0, a3 = 0;
            const float* Hc = Hs + (s * 64) * HSTR + n;
            const float4* wv4 = (const float4*)(w128 + s * 64);
#pragma unroll
            for (int t = 0; t < 16; t++) {
                float4 wv = wv4[t];
                a0 += Hc[(4 * t + 0) * HSTR] * wv.x;
                a1 += Hc[(4 * t + 1) * HSTR] * wv.y;
                a2 += Hc[(4 * t + 2) * HSTR] * wv.z;
                a3 += Hc[(4 * t + 3) * HSTR] * wv.w;
            }
            red[tid] = (a0 + a1) + (a2 + a3);
        }
        __syncthreads();
        if (tid < 64) {
            float u = red[tid] + red[tid + 64];
            t64[tid] = u;
            red[tid] = u * u;
        }
        __syncthreads();
        if (tid < 32) {
            float ss = red[tid] + red[tid + 32];
#pragma unroll
            for (int o = 16; o; o >>= 1) ss += __shfl_down_sync(0xffffffffu, ss, o);
            if (tid == 0) scal[0] = 1.f / (sqrtf(ss) + 1e-12f);
        }
        __syncthreads();
        if (tid < 64) v64[tid] = t64[tid] * scal[0];
        __syncthreads();
    }

    {
        float c0 = 0, c1 = 0, c2 = 0, c3 = 0;
#pragma unroll
        for (int t = 0; t < 16; t++) {
            float4 vv = *(const float4*)&v64[4 * t];
            c0 += Hrow[4 * t + 0] * vv.x;
            c1 += Hrow[4 * t + 1] * vv.y;
            c2 += Hrow[4 * t + 2] * vv.z;
            c3 += Hrow[4 * t + 3] * vv.w;
        }
        float hv = (c0 + c1) + (c2 + c3);
        red[tid] = hv * hv;
    }
    __syncthreads();
    if (tid < 32) {
        float ss = red[tid] + red[tid + 32] + red[tid + 64] + red[tid + 96];
#pragma unroll
        for (int o = 16; o; o >>= 1) ss += __shfl_down_sync(0xffffffffu, ss, o);
        if (tid == 0) scal[1] = 0.9f / (sqrtf(ss) + 1e-6f);
    }
    __syncthreads();
    const float tau = scal[1];

    for (int p = tid; p < 64 * 64; p += 128) {
        int i = p >> 6, j = p & 63;
        if (j <= i)
            Ainv[i * ASTR + j] = tau * Ainv[i * ASTR + j] + (i == j ? 1.f : 0.f);
    }
    __syncthreads();

    {
        const int i = n;
        for (int k = 0; k < 64; k++) {
            if (tid < 64)
                colk[tid] = (tid >= k) ? Ainv[tid * ASTR + k] : Ainv[k * ASTR + tid];
            __syncthreads();
            const float pinv = 1.f / colk[k];
            const float ci = colk[i] * pinv;
            for (int c = s; 4 * c <= i; c += 2) {
                float4 cj = *(const float4*)&colk[4 * c];
                float4 a = *(float4*)&Ainv[i * ASTR + 4 * c];
                a.x -= ci * cj.x; a.y -= ci * cj.y;
                a.z -= ci * cj.z; a.w -= ci * cj.w;
                *(float4*)&Ainv[i * ASTR + 4 * c] = a;
            }
            __syncthreads();
            if (tid < 64) {
                if (tid > k)      Ainv[tid * ASTR + k] = colk[tid] * pinv;
                else if (tid < k) Ainv[k * ASTR + tid] = colk[tid] * pinv;
                else              Ainv[k * ASTR + k]   = -pinv;
            }
            __syncthreads();
        }
    }

    float Mreg[32];
    {
        const int base = s * 32;
#pragma unroll
        for (int t = 0; t < 32; t++) {
            int kk = base + t;
            Mreg[t] = (kk >= n) ? Ainv[kk * ASTR + n] : Ainv[n * ASTR + kk];
        }
    }

    float lamr = 0.f;
    float xpr = 0.f;
    if (tid < 64) xbar[tid] = 0.f;
    __syncthreads();

    for (int it = 0; it < QPIT; ++it) {
        float c0 = 0, c1 = 0, c2 = 0, c3 = 0;
#pragma unroll
        for (int t = 0; t < 16; t++) {
            float4 xv = *(const float4*)&xbar[4 * t];
            c0 += Hrow[4 * t + 0] * xv.x;
            c1 += Hrow[4 * t + 1] * xv.y;
            c2 += Hrow[4 * t + 2] * xv.z;
            c3 += Hrow[4 * t + 3] * xv.w;
        }
        float hx = (c0 + c1) + (c2 + c3);
        lamr = fmaxf(lamr - tau * (hx + br), 0.f);
        lam[tid] = lamr;
        __syncthreads();

        {
            float a0 = 0, a1 = 0, a2 = 0, a3 = 0;
            const float* Hc = Hs + (s * 64) * HSTR + n;
            const float4* lv4 = (const float4*)(lam + s * 64);
#pragma unroll
            for (int t = 0; t < 16; t++) {
                float4 lv = lv4[t];
                a0 += Hc[(4 * t + 0) * HSTR] * lv.x;
                a1 += Hc[(4 * t + 1) * HSTR] * lv.y;
                a2 += Hc[(4 * t + 2) * HSTR] * lv.z;
                a3 += Hc[(4 * t + 3) * HSTR] * lv.w;
            }
            red[tid] = (a0 + a1) + (a2 + a3);
        }
        __syncthreads();
        if (tid < 64)
            rhs[tid] = xpr + tau * ((red[tid] + red[tid + 64]) - qr);
        __syncthreads();

        {
            float a0 = 0, a1 = 0, a2 = 0, a3 = 0;
            const float4* rv4 = (const float4*)(rhs + s * 32);
#pragma unroll
            for (int t = 0; t < 8; t++) {
                float4 rv = rv4[t];
                a0 += Mreg[4 * t + 0] * rv.x;
                a1 += Mreg[4 * t + 1] * rv.y;
                a2 += Mreg[4 * t + 2] * rv.z;
                a3 += Mreg[4 * t + 3] * rv.w;
            }
            red[tid] = (a0 + a1) + (a2 + a3);
        }
        __syncthreads();
        if (tid < 64) {
            float xn = -(red[tid] + red[tid + 64]);
            xbar[tid] = 2.f * xn - xpr;
            xpr = xn;
        }
        __syncthreads();
    }

    if (tid < 64) xs[(size_t)blockIdx.x * NQP + tid] = xpr;
}

// ---------------------------------------------------------------------------
extern "C" void kernel_launch(void* const* d_in, const int* in_sizes, int n_in,
                              void* d_out, int out_size)
{
    const float* x  = (const float*)d_in[0];
    const float* W1 = (const float*)d_in[1];
    const float* b1 = (const float*)d_in[2];
    const float* W2 = (const float*)d_in[3];
    const float* b2 = (const float*)d_in[4];
    const float* W3 = (const float*)d_in[5];
    const float* b3 = (const float*)d_in[6];
    float* xs = (float*)d_out;

    __nv_bfloat16 *xhi, *xlo, *w1h, *w1l, *w2h, *w2l, *w3h, *w3l;
    __nv_bfloat16 *h1h, *h1l, *h2h, *h2l;
    float* obuf;
    cudaGetSymbolAddress((void**)&xhi, g_xhi);
    cudaGetSymbolAddress((void**)&xlo, g_xlo);
    cudaGetSymbolAddress((void**)&w1h, g_w1thi);
    cudaGetSymbolAddress((void**)&w1l, g_w1tlo);
    cudaGetSymbolAddress((void**)&w2h, g_w2thi);
    cudaGetSymbolAddress((void**)&w2l, g_w2tlo);
    cudaGetSymbolAddress((void**)&w3h, g_w3thi);
    cudaGetSymbolAddress((void**)&w3l, g_w3tlo);
    cudaGetSymbolAddress((void**)&h1h, g_h1hi);
    cudaGetSymbolAddress((void**)&h1l, g_h1lo);
    cudaGetSymbolAddress((void**)&h2h, g_h2hi);
    cudaGetSymbolAddress((void**)&h2l, g_h2lo);
    cudaGetSymbolAddress((void**)&obuf, g_out);

    cudaFuncSetAttribute(gemm_split_kernel,
                         cudaFuncAttributeMaxDynamicSharedMemorySize, GSMEM);
    const int ssmem = SOLVER_SMEM_FLOATS * (int)sizeof(float);
    cudaFuncSetAttribute(solver_kernel,
                         cudaFuncAttributeMaxDynamicSharedMemorySize, ssmem);

    // input prep: split x; transpose+split weights
    split_kernel<<<512, 256>>>(x, xhi, xlo, BATCH * INSZ);
    tsplit_kernel<<<dim3(HID / 32, INSZ / 32), dim3(32, 8)>>>(W1, w1h, w1l, INSZ, HID);
    tsplit_kernel<<<dim3(HID / 32, HID / 32), dim3(32, 8)>>>(W2, w2h, w2l, HID, HID);
    tsplit_kernel<<<dim3(NOUT / 32, HID / 32), dim3(32, 8)>>>(W3, w3h, w3l, HID, NOUT);

    // MLP on tensor cores (mma.sync bf16, 3-term split, term-major issue)
    gemm_split_kernel<<<dim3(8, 8), 256, GSMEM>>>(
        xhi, xlo, w1h, w1l, b1, nullptr, h1h, h1l, BATCH, HID, INSZ, 1);
    gemm_split_kernel<<<dim3(8, 8), 256, GSMEM>>>(
        h1h, h1l, w2h, w2l, b2, nullptr, h2h, h2l, BATCH, HID, HID, 1);
    gemm_split_kernel<<<dim3((NOUT + 127) / 128, 8), 256, GSMEM>>>(
        h2h, h2l, w3h, w3l, b3, obuf, nullptr, nullptr, BATCH, NOUT, HID, 0);

    solver_kernel<<<1024, 128, ssmem>>>(obuf, xs);
}